// round 14
// baseline (speedup 1.0000x reference)
#include <cuda_runtime.h>
#include <cuda_fp16.h>
#include <cstdint>

#define NP   100000
#define RREL 3
#define NE   1600000
#define EPC  500000
#define FIN  128
#define FH   64
#define NDST (RREL * NP)          // 300000 scanned rows
#define SCAN_BLK 512
#define SCAN_NB  ((NDST + SCAN_BLK - 1) / SCAN_BLK)   // 586
#define MBLK 782                  // ceil(NP/128)

// ---------------- device scratch (static, allocation-free) ----------------
__device__ int    g_cnt[6 * NP];          // [0:3N) src counts, [3N:6N) dst counts
__device__ float  g_rs [6 * NP];          // rsqrt(max(count,1)) same layout
__device__ __half g_hh[RREL * NP * FH];   // per-relation projected features, fp16 (reused layer 2)
__device__ float  g_h1 [NP * FH];         // relu(hetero_conv1), fp32
__device__ int    g_rowptr[NDST + 1];     // CSR row pointers (relations concatenated)
__device__ int    g_cursor[NDST];         // fill cursors
__device__ int    g_csr[RREL * NE];       // src node per in-edge, grouped by (rel,dst)
__device__ int    g_bsum[SCAN_NB];        // scan spine

// Threefry-2x32, 20 rounds, key = (0, 42)  (jax.random.key(42))
__device__ __forceinline__ void threefry_0_42(uint32_t x0, uint32_t x1,
                                              uint32_t& o0, uint32_t& o1) {
    const uint32_t k0 = 0u, k1 = 42u, k2 = 0x1BD11BDAu ^ 0u ^ 42u;
    x0 += k0; x1 += k1;
#define TF_RND(Rv) { x0 += x1; x1 = __funnelshift_l(x1, x1, (Rv)); x1 ^= x0; }
    TF_RND(13) TF_RND(15) TF_RND(26) TF_RND(6)   x0 += k1; x1 += k2 + 1u;
    TF_RND(17) TF_RND(29) TF_RND(16) TF_RND(24)  x0 += k2; x1 += k0 + 2u;
    TF_RND(13) TF_RND(15) TF_RND(26) TF_RND(6)   x0 += k0; x1 += k1 + 3u;
    TF_RND(17) TF_RND(29) TF_RND(16) TF_RND(24)  x0 += k1; x1 += k2 + 4u;
    TF_RND(13) TF_RND(15) TF_RND(26) TF_RND(6)   x0 += k2; x1 += k0 + 5u;
#undef TF_RND
    o0 = x0; o1 = x1;
}

// bits -> jax-style standard normal (uniform in [lo,1) then sqrt(2)*erfinv)
__device__ __forceinline__ float jax_normal(uint32_t bits) {
    const float LO = -0.99999994f;
    float f = __uint_as_float((bits >> 9) | 0x3f800000u) - 1.0f;
    float u = fmaxf(f * 2.0f + LO, LO);
    return 1.41421356237309515f * erfinvf(u);
}

__device__ __forceinline__ uint32_t f2tf32(float f) {
    uint32_t r;
    asm("cvt.rna.tf32.f32 %0, %1;" : "=r"(r) : "f"(f));
    return r;
}

__device__ __forceinline__ void mma_tf32(float& c0, float& c1, float& c2, float& c3,
                                         uint32_t a0, uint32_t a1, uint32_t a2, uint32_t a3,
                                         uint32_t b0, uint32_t b1) {
    asm volatile("mma.sync.aligned.m16n8k8.row.col.f32.tf32.tf32.f32 "
                 "{%0,%1,%2,%3},{%4,%5,%6,%7},{%8,%9},{%0,%1,%2,%3};"
                 : "+f"(c0), "+f"(c1), "+f"(c2), "+f"(c3)
                 : "r"(a0), "r"(a1), "r"(a2), "r"(a3), "r"(b0), "r"(b1));
}

// ---------------- setup kernels ----------------
__global__ void zero_kernel() {
    int i = blockIdx.x * 256 + threadIdx.x;
    if (i < 6 * NP) g_cnt[i] = 0;
}

__global__ void deg_kernel(const int* __restrict__ es, const int* __restrict__ ed) {
    int i = blockIdx.x * 256 + threadIdx.x;
    if (i >= RREL * NE) return;
    int r = i / NE;
    atomicAdd(&g_cnt[r * NP + es[i]], 1);
    atomicAdd(&g_cnt[3 * NP + r * NP + ed[i]], 1);
}

// ---- 3-kernel exclusive scan over dst counts ----
__global__ void scan_blocksum_kernel() {
    __shared__ int sm[SCAN_BLK];
    int i = blockIdx.x * SCAN_BLK + threadIdx.x;
    int v = (i < NDST) ? g_cnt[3 * NP + i] : 0;
    sm[threadIdx.x] = v;
    __syncthreads();
    for (int off = SCAN_BLK / 2; off > 0; off >>= 1) {
        if (threadIdx.x < off) sm[threadIdx.x] += sm[threadIdx.x + off];
        __syncthreads();
    }
    if (threadIdx.x == 0) g_bsum[blockIdx.x] = sm[0];
}

__global__ void scan_spine_kernel() {
    __shared__ int sm[1024];
    int t = threadIdx.x;
    int v = (t < SCAN_NB) ? g_bsum[t] : 0;
    sm[t] = v;
    __syncthreads();
    for (int off = 1; off < 1024; off <<= 1) {
        int add = (t >= off) ? sm[t - off] : 0;
        __syncthreads();
        sm[t] += add;
        __syncthreads();
    }
    if (t < SCAN_NB) g_bsum[t] = sm[t] - v;   // exclusive
}

__global__ void scan_apply_kernel() {
    __shared__ int sm[SCAN_BLK];
    int i = blockIdx.x * SCAN_BLK + threadIdx.x;
    int t = threadIdx.x;
    int v = (i < NDST) ? g_cnt[3 * NP + i] : 0;
    sm[t] = v;
    __syncthreads();
    for (int off = 1; off < SCAN_BLK; off <<= 1) {
        int add = (t >= off) ? sm[t - off] : 0;
        __syncthreads();
        sm[t] += add;
        __syncthreads();
    }
    if (i < NDST) {
        int excl = g_bsum[blockIdx.x] + sm[t] - v;
        g_rowptr[i] = excl;
        g_cursor[i] = excl;
        g_rs[i]          = rsqrtf(fmaxf((float)g_cnt[i], 1.0f));
        g_rs[3 * NP + i] = rsqrtf(fmaxf((float)v, 1.0f));
    }
    if (i == 0) g_rowptr[NDST] = RREL * NE;
}

__global__ void fill_csr_kernel(const int* __restrict__ es, const int* __restrict__ ed) {
    int i = blockIdx.x * 256 + threadIdx.x;
    if (i >= RREL * NE) return;
    int r = i / NE;
    int pos = atomicAdd(&g_cursor[r * NP + ed[i]], 1);
    g_csr[pos] = es[i];
}

// ---------------- layer-1 projection: tf32 MMA, x staged ONCE, 3 relations in-block ----------------
// rs is a row scalar: (x*rs_r)@W_r = rs_r * (x@W_r) -> stage raw x, scale in epilogue.
// Tile 128(M) x 64(N) x 3(R), K chunked x32. 8 warps; warp w owns rows [16w,16w+16).
#define XS_STR 36
#define WS_STR 72
__global__ void __launch_bounds__(256, 1) proj1_kernel(const float* __restrict__ x,
                                                       const float* __restrict__ W0) {
    __shared__ uint32_t xs[128 * XS_STR];   // raw x, tf32 bits, 18.4 KB
    __shared__ uint32_t Ws[32 * WS_STR];    // W_r chunk, tf32 bits, 9.2 KB
    const int t = threadIdx.x, m0 = blockIdx.x * 128;
    const int lane = t & 31, w = t >> 5;
    const int g = lane >> 2, t4 = lane & 3;

    float c[RREL][8][4];
#pragma unroll
    for (int r = 0; r < RREL; ++r)
#pragma unroll
        for (int j = 0; j < 8; ++j)
#pragma unroll
            for (int q = 0; q < 4; ++q) c[r][j][q] = 0.f;

    const float4* x4 = (const float4*)x;
    const int rowA = (w * 16 + g) * XS_STR;

    for (int cch = 0; cch < 4; ++cch) {
        // stage RAW x[:, cch*32 : +32] as tf32 (no per-relation scale)
#pragma unroll
        for (int it = 0; it < 4; ++it) {
            int idx = t + it * 256;
            int row = idx >> 3, q = idx & 7;
            int m = m0 + row;
            float4 v = make_float4(0.f, 0.f, 0.f, 0.f);
            if (m < NP) v = x4[m * 32 + cch * 8 + q];
            uint32_t* p = &xs[row * XS_STR + q * 4];
            p[0] = f2tf32(v.x); p[1] = f2tf32(v.y);
            p[2] = f2tf32(v.z); p[3] = f2tf32(v.w);
        }
        __syncthreads();

        for (int r = 0; r < RREL; ++r) {
            const float* W = W0 + r * FIN * FH + cch * 2048;
#pragma unroll
            for (int i = t; i < 32 * 64; i += 256)
                Ws[(i >> 6) * WS_STR + (i & 63)] = f2tf32(W[i]);
            __syncthreads();

#pragma unroll
            for (int ks = 0; ks < 4; ++ks) {
                const int kc = ks * 8;
                uint32_t a0 = xs[rowA + kc + t4];
                uint32_t a1 = xs[rowA + 8 * XS_STR + kc + t4];
                uint32_t a2 = xs[rowA + kc + t4 + 4];
                uint32_t a3 = xs[rowA + 8 * XS_STR + kc + t4 + 4];
                const int kb = (kc + t4) * WS_STR + g;
#pragma unroll
                for (int j = 0; j < 8; ++j) {
                    uint32_t b0 = Ws[kb + j * 8];
                    uint32_t b1 = Ws[kb + 4 * WS_STR + j * 8];
                    mma_tf32(c[r][j][0], c[r][j][1], c[r][j][2], c[r][j][3],
                             a0, a1, a2, a3, b0, b1);
                }
            }
            __syncthreads();
        }
    }

    // epilogue: scale by rs_r[row], pack half2
    __half2* oh = (__half2*)g_hh;
    const int row0 = m0 + w * 16 + g;
#pragma unroll
    for (int r = 0; r < RREL; ++r) {
        float s_lo = (row0 < NP)     ? g_rs[r * NP + row0]     : 0.f;
        float s_hi = (row0 + 8 < NP) ? g_rs[r * NP + row0 + 8] : 0.f;
#pragma unroll
        for (int j = 0; j < 8; ++j) {
            int h2i = j * 4 + t4;
            if (row0 < NP)
                oh[(r * NP + row0) * 32 + h2i] =
                    __floats2half2_rn(c[r][j][0] * s_lo, c[r][j][1] * s_lo);
            if (row0 + 8 < NP)
                oh[(r * NP + row0 + 8) * 32 + h2i] =
                    __floats2half2_rn(c[r][j][2] * s_hi, c[r][j][3] * s_hi);
        }
    }
}

// ---------------- layer-1 gather: lane = half2 (dims 2l, 2l+1); 128B/warp/edge ----------------
__global__ void __launch_bounds__(256) gather1_kernel(const float* __restrict__ b0) {
    int w = (blockIdx.x * 256 + threadIdx.x) >> 5;   // dst node
    int lane = threadIdx.x & 31;
    if (w >= NP) return;
    float a0 = 0.f, a1 = 0.f;
#pragma unroll
    for (int r = 0; r < RREL; ++r) {
        int beg = g_rowptr[r * NP + w];
        int end = g_rowptr[r * NP + w + 1];
        float sc = g_rs[3 * NP + r * NP + w];
        const __half2* hb = (const __half2*)(g_hh + (size_t)r * NP * FH);
        float s0 = 0.f, s1 = 0.f;
        int e = beg;
        for (; e + 4 <= end; e += 4) {
            int i0 = g_csr[e], i1 = g_csr[e + 1], i2 = g_csr[e + 2], i3 = g_csr[e + 3];
            float2 v0 = __half22float2(hb[i0 * 32 + lane]);
            float2 v1 = __half22float2(hb[i1 * 32 + lane]);
            float2 v2 = __half22float2(hb[i2 * 32 + lane]);
            float2 v3 = __half22float2(hb[i3 * 32 + lane]);
            s0 += (v0.x + v1.x) + (v2.x + v3.x);
            s1 += (v0.y + v1.y) + (v2.y + v3.y);
        }
        for (; e < end; ++e) {
            float2 v = __half22float2(hb[g_csr[e] * 32 + lane]);
            s0 += v.x; s1 += v.y;
        }
        a0 = fmaf(sc, s0, a0);
        a1 = fmaf(sc, s1, a1);
    }
    int f = 2 * lane;
    float o0 = fmaxf(a0 + b0[f]     + b0[FH + f]     + b0[2 * FH + f],     0.f);
    float o1 = fmaxf(a1 + b0[f + 1] + b0[FH + f + 1] + b0[2 * FH + f + 1], 0.f);
    *(float2*)&g_h1[w * FH + f] = make_float2(o0, o1);
}

// ---------------- layer-2 projection: tf32 MMA, h1 staged ONCE, 3 relations in-block ----------------
// Tile 128(M) x 32(N) x 3(R), K=64. Ws cols: [0:16)=W_mu, [16:32)=W_ls.
#define X2_STR 68
#define W2_STR 40
__global__ void __launch_bounds__(256, 1) proj2_kernel(const float* __restrict__ Wmu,
                                                       const float* __restrict__ Wls) {
    __shared__ uint32_t xs[128 * X2_STR];   // raw h1, 34.8 KB
    __shared__ uint32_t Ws[64 * W2_STR];    // 10.2 KB
    const int t = threadIdx.x, m0 = blockIdx.x * 128;
    const int lane = t & 31, w = t >> 5;
    const int g = lane >> 2, t4 = lane & 3;

    // stage raw h1 once
    const float4* h4 = (const float4*)g_h1;
#pragma unroll
    for (int it = 0; it < 8; ++it) {
        int idx = t + it * 256;
        int row = idx >> 4, q = idx & 15;
        int m = m0 + row;
        float4 v = make_float4(0.f, 0.f, 0.f, 0.f);
        if (m < NP) v = h4[m * 16 + q];
        uint32_t* p = &xs[row * X2_STR + q * 4];
        p[0] = f2tf32(v.x); p[1] = f2tf32(v.y);
        p[2] = f2tf32(v.z); p[3] = f2tf32(v.w);
    }
    __syncthreads();

    float c[RREL][4][4];
#pragma unroll
    for (int r = 0; r < RREL; ++r)
#pragma unroll
        for (int j = 0; j < 4; ++j)
#pragma unroll
            for (int q = 0; q < 4; ++q) c[r][j][q] = 0.f;

    const int rowA = (w * 16 + g) * X2_STR;

    for (int r = 0; r < RREL; ++r) {
        for (int i = t; i < 64 * 16; i += 256) {
            int k = i >> 4, cc = i & 15;
            Ws[k * W2_STR + cc]      = f2tf32(Wmu[r * 1024 + i]);
            Ws[k * W2_STR + 16 + cc] = f2tf32(Wls[r * 1024 + i]);
        }
        __syncthreads();

#pragma unroll
        for (int ks = 0; ks < 8; ++ks) {
            const int kc = ks * 8;
            uint32_t a0 = xs[rowA + kc + t4];
            uint32_t a1 = xs[rowA + 8 * X2_STR + kc + t4];
            uint32_t a2 = xs[rowA + kc + t4 + 4];
            uint32_t a3 = xs[rowA + 8 * X2_STR + kc + t4 + 4];
            const int kb = (kc + t4) * W2_STR + g;
#pragma unroll
            for (int j = 0; j < 4; ++j) {
                uint32_t b0 = Ws[kb + j * 8];
                uint32_t b1 = Ws[kb + 4 * W2_STR + j * 8];
                mma_tf32(c[r][j][0], c[r][j][1], c[r][j][2], c[r][j][3],
                         a0, a1, a2, a3, b0, b1);
            }
        }
        __syncthreads();
    }

    // epilogue: scale by rs_r[row], pack half2 (row = 16 half2)
    __half2* oh = (__half2*)g_hh;
    const int row0 = m0 + w * 16 + g;
#pragma unroll
    for (int r = 0; r < RREL; ++r) {
        float s_lo = (row0 < NP)     ? g_rs[r * NP + row0]     : 0.f;
        float s_hi = (row0 + 8 < NP) ? g_rs[r * NP + row0 + 8] : 0.f;
#pragma unroll
        for (int j = 0; j < 4; ++j) {
            int h2i = j * 4 + t4;
            if (row0 < NP)
                oh[(r * NP + row0) * 16 + h2i] =
                    __floats2half2_rn(c[r][j][0] * s_lo, c[r][j][1] * s_lo);
            if (row0 + 8 < NP)
                oh[(r * NP + row0 + 8) * 16 + h2i] =
                    __floats2half2_rn(c[r][j][2] * s_hi, c[r][j][3] * s_hi);
        }
    }
}

// ---------------- layer-2 gather — fp16 rows (64B/edge), fused reparameterization ----------------
__global__ void __launch_bounds__(256) gather2_kernel(const float* __restrict__ bmu,
                                                      const float* __restrict__ bls,
                                                      float* __restrict__ out) {
    int w = (blockIdx.x * 256 + threadIdx.x) >> 5;   // dst node
    int lane = threadIdx.x & 31;
    if (w >= NP) return;
    float acc = 0.f;
#pragma unroll
    for (int r = 0; r < RREL; ++r) {
        int beg = g_rowptr[r * NP + w];
        int end = g_rowptr[r * NP + w + 1];
        float sc = g_rs[3 * NP + r * NP + w];
        const __half* hb = g_hh + (size_t)r * NP * 32;
        float s0 = 0.f;
        int e = beg;
        for (; e + 4 <= end; e += 4) {
            int i0 = g_csr[e], i1 = g_csr[e + 1], i2 = g_csr[e + 2], i3 = g_csr[e + 3];
            float v0 = __half2float(hb[i0 * 32 + lane]);
            float v1 = __half2float(hb[i1 * 32 + lane]);
            float v2 = __half2float(hb[i2 * 32 + lane]);
            float v3 = __half2float(hb[i3 * 32 + lane]);
            s0 += (v0 + v1) + (v2 + v3);
        }
        for (; e < end; ++e) s0 += __half2float(hb[g_csr[e] * 32 + lane]);
        acc = fmaf(sc, s0, acc);
    }
    float bias = (lane < 16)
        ? (bmu[lane] + bmu[16 + lane] + bmu[32 + lane])
        : (bls[lane - 16] + bls[lane] + bls[lane + 16]);
    float val = acc + bias;
    float ls  = __shfl_sync(0xffffffffu, val, (lane + 16) & 31);
    uint32_t o0, o1;
    threefry_0_42(0u, (uint32_t)(w * 16 + lane), o0, o1);
    if (lane < 16)
        out[1000000 + w * 16 + lane] = val + jax_normal(o0 ^ o1) * expf(ls);
}

__global__ void score_kernel(const int* __restrict__ ps, const int* __restrict__ pd,
                             const int* __restrict__ ns, const int* __restrict__ nd,
                             float* __restrict__ out) {
    int i = blockIdx.x * 256 + threadIdx.x;
    if (i >= 2 * EPC) return;
    int s, d;
    if (i < EPC) { s = ps[i]; d = pd[i]; }
    else         { s = ns[i - EPC]; d = nd[i - EPC]; }
    const float4* h4 = (const float4*)(out + 1000000);
    float acc = 0.f;
#pragma unroll
    for (int q = 0; q < 4; ++q) {
        float4 a = h4[s * 4 + q], b = h4[d * 4 + q];
        acc += a.x * b.x + a.y * b.y + a.z * b.z + a.w * b.w;
    }
    out[i] = acc;
}

// ---------------- launch ----------------
extern "C" void kernel_launch(void* const* d_in, const int* in_sizes, int n_in,
                              void* d_out, int out_size) {
    const float* x   = (const float*)d_in[0];
    const float* W0  = (const float*)d_in[1];
    const float* b0  = (const float*)d_in[2];
    const float* Wmu = (const float*)d_in[3];
    const float* bmu = (const float*)d_in[4];
    const float* Wls = (const float*)d_in[5];
    const float* bls = (const float*)d_in[6];
    const int*   es  = (const int*)d_in[7];
    const int*   ed  = (const int*)d_in[8];
    const int*   ps  = (const int*)d_in[9];
    const int*   pd  = (const int*)d_in[10];
    const int*   ns  = (const int*)d_in[11];
    const int*   nd  = (const int*)d_in[12];
    float* out = (float*)d_out;

    const int GBLK = (NP * 32 + 255) / 256;       // warp-per-node grids

    zero_kernel         <<<(6 * NP + 255) / 256, 256>>>();
    deg_kernel          <<<(RREL * NE + 255) / 256, 256>>>(es, ed);
    scan_blocksum_kernel<<<SCAN_NB, SCAN_BLK>>>();
    scan_spine_kernel   <<<1, 1024>>>();
    scan_apply_kernel   <<<SCAN_NB, SCAN_BLK>>>();
    fill_csr_kernel     <<<(RREL * NE + 255) / 256, 256>>>(es, ed);
    proj1_kernel        <<<MBLK, 256>>>(x, W0);
    gather1_kernel      <<<GBLK, 256>>>(b0);
    proj2_kernel        <<<MBLK, 256>>>(Wmu, Wls);
    gather2_kernel      <<<GBLK, 256>>>(bmu, bls, out);
    score_kernel        <<<(2 * EPC + 255) / 256, 256>>>(ps, pd, ns, nd, out);
}

// round 15
// speedup vs baseline: 1.0153x; 1.0153x over previous
#include <cuda_runtime.h>
#include <cuda_fp16.h>
#include <cstdint>

#define NP   100000
#define RREL 3
#define NE   1600000
#define EPC  500000
#define FIN  128
#define FH   64
#define NDST (RREL * NP)          // 300000 scanned rows
#define SCAN_BLK 512
#define SCAN_NB  ((NDST + SCAN_BLK - 1) / SCAN_BLK)   // 586
#define MBLK 782                  // ceil(NP/128)

// ---------------- device scratch (static, allocation-free) ----------------
__device__ int    g_cnt[6 * NP];          // [0:3N) src counts, [3N:6N) dst counts
__device__ float  g_rs [6 * NP];          // rsqrt(max(count,1)) same layout
__device__ __half g_hh[RREL * NP * FH];   // per-relation projected features, fp16 (reused layer 2)
__device__ float  g_h1 [NP * FH];         // relu(hetero_conv1), fp32
__device__ int    g_rowptr[NDST + 1];     // CSR row pointers (relations concatenated)
__device__ int    g_cursor[NDST];         // fill cursors
__device__ int    g_csr[RREL * NE];       // src node per in-edge, grouped by (rel,dst)
__device__ int    g_bsum[SCAN_NB];        // scan spine

// Threefry-2x32, 20 rounds, key = (0, 42)  (jax.random.key(42))
__device__ __forceinline__ void threefry_0_42(uint32_t x0, uint32_t x1,
                                              uint32_t& o0, uint32_t& o1) {
    const uint32_t k0 = 0u, k1 = 42u, k2 = 0x1BD11BDAu ^ 0u ^ 42u;
    x0 += k0; x1 += k1;
#define TF_RND(Rv) { x0 += x1; x1 = __funnelshift_l(x1, x1, (Rv)); x1 ^= x0; }
    TF_RND(13) TF_RND(15) TF_RND(26) TF_RND(6)   x0 += k1; x1 += k2 + 1u;
    TF_RND(17) TF_RND(29) TF_RND(16) TF_RND(24)  x0 += k2; x1 += k0 + 2u;
    TF_RND(13) TF_RND(15) TF_RND(26) TF_RND(6)   x0 += k0; x1 += k1 + 3u;
    TF_RND(17) TF_RND(29) TF_RND(16) TF_RND(24)  x0 += k1; x1 += k2 + 4u;
    TF_RND(13) TF_RND(15) TF_RND(26) TF_RND(6)   x0 += k2; x1 += k0 + 5u;
#undef TF_RND
    o0 = x0; o1 = x1;
}

// bits -> jax-style standard normal (uniform in [lo,1) then sqrt(2)*erfinv)
__device__ __forceinline__ float jax_normal(uint32_t bits) {
    const float LO = -0.99999994f;
    float f = __uint_as_float((bits >> 9) | 0x3f800000u) - 1.0f;
    float u = fmaxf(f * 2.0f + LO, LO);
    return 1.41421356237309515f * erfinvf(u);
}

__device__ __forceinline__ uint32_t f2tf32(float f) {
    uint32_t r;
    asm("cvt.rna.tf32.f32 %0, %1;" : "=r"(r) : "f"(f));
    return r;
}

__device__ __forceinline__ void mma_tf32(float& c0, float& c1, float& c2, float& c3,
                                         uint32_t a0, uint32_t a1, uint32_t a2, uint32_t a3,
                                         uint32_t b0, uint32_t b1) {
    asm volatile("mma.sync.aligned.m16n8k8.row.col.f32.tf32.tf32.f32 "
                 "{%0,%1,%2,%3},{%4,%5,%6,%7},{%8,%9},{%0,%1,%2,%3};"
                 : "+f"(c0), "+f"(c1), "+f"(c2), "+f"(c3)
                 : "r"(a0), "r"(a1), "r"(a2), "r"(a3), "r"(b0), "r"(b1));
}

// ---------------- setup kernels ----------------
__global__ void zero_kernel() {
    int i = blockIdx.x * 256 + threadIdx.x;
    if (i < 6 * NP) g_cnt[i] = 0;
}

__global__ void deg_kernel(const int* __restrict__ es, const int* __restrict__ ed) {
    int i = blockIdx.x * 256 + threadIdx.x;
    if (i >= RREL * NE) return;
    int r = i / NE;
    atomicAdd(&g_cnt[r * NP + es[i]], 1);
    atomicAdd(&g_cnt[3 * NP + r * NP + ed[i]], 1);
}

// ---- 3-kernel exclusive scan over dst counts ----
__global__ void scan_blocksum_kernel() {
    __shared__ int sm[SCAN_BLK];
    int i = blockIdx.x * SCAN_BLK + threadIdx.x;
    int v = (i < NDST) ? g_cnt[3 * NP + i] : 0;
    sm[threadIdx.x] = v;
    __syncthreads();
    for (int off = SCAN_BLK / 2; off > 0; off >>= 1) {
        if (threadIdx.x < off) sm[threadIdx.x] += sm[threadIdx.x + off];
        __syncthreads();
    }
    if (threadIdx.x == 0) g_bsum[blockIdx.x] = sm[0];
}

__global__ void scan_spine_kernel() {
    __shared__ int sm[1024];
    int t = threadIdx.x;
    int v = (t < SCAN_NB) ? g_bsum[t] : 0;
    sm[t] = v;
    __syncthreads();
    for (int off = 1; off < 1024; off <<= 1) {
        int add = (t >= off) ? sm[t - off] : 0;
        __syncthreads();
        sm[t] += add;
        __syncthreads();
    }
    if (t < SCAN_NB) g_bsum[t] = sm[t] - v;   // exclusive
}

__global__ void scan_apply_kernel() {
    __shared__ int sm[SCAN_BLK];
    int i = blockIdx.x * SCAN_BLK + threadIdx.x;
    int t = threadIdx.x;
    int v = (i < NDST) ? g_cnt[3 * NP + i] : 0;
    sm[t] = v;
    __syncthreads();
    for (int off = 1; off < SCAN_BLK; off <<= 1) {
        int add = (t >= off) ? sm[t - off] : 0;
        __syncthreads();
        sm[t] += add;
        __syncthreads();
    }
    if (i < NDST) {
        int excl = g_bsum[blockIdx.x] + sm[t] - v;
        g_rowptr[i] = excl;
        g_cursor[i] = excl;
        g_rs[i]          = rsqrtf(fmaxf((float)g_cnt[i], 1.0f));
        g_rs[3 * NP + i] = rsqrtf(fmaxf((float)v, 1.0f));
    }
    if (i == 0) g_rowptr[NDST] = RREL * NE;
}

__global__ void fill_csr_kernel(const int* __restrict__ es, const int* __restrict__ ed) {
    int i = blockIdx.x * 256 + threadIdx.x;
    if (i >= RREL * NE) return;
    int r = i / NE;
    int pos = atomicAdd(&g_cursor[r * NP + ed[i]], 1);
    g_csr[pos] = es[i];
}

// ---------------- layer-1 projection: tf32 tensor-core MMA, fp16 output (R13 form) ----------------
// Tile 128(M) x 64(N), K chunked x32. 8 warps, warp w owns rows [16w,16w+16).
#define XS_STR 36
#define WS_STR 72
__global__ void __launch_bounds__(256) proj1_kernel(const float* __restrict__ x,
                                                    const float* __restrict__ W0) {
    __shared__ uint32_t xs[128 * XS_STR];   // tf32 bits, 18.4 KB
    __shared__ uint32_t Ws[32 * WS_STR];    // tf32 bits, 9.2 KB
    const int r = blockIdx.y, t = threadIdx.x, m0 = blockIdx.x * 128;
    const int lane = t & 31, w = t >> 5;
    const int g = lane >> 2, t4 = lane & 3;

    float c[8][4];
#pragma unroll
    for (int j = 0; j < 8; ++j)
#pragma unroll
        for (int q = 0; q < 4; ++q) c[j][q] = 0.f;

    const float4* x4 = (const float4*)x;
    const float* W = W0 + r * FIN * FH;
    const int rowA = (w * 16 + g) * XS_STR;

    for (int cch = 0; cch < 4; ++cch) {
#pragma unroll
        for (int it = 0; it < 4; ++it) {
            int idx = t + it * 256;
            int row = idx >> 3, q = idx & 7;
            int m = m0 + row;
            float4 v = make_float4(0.f, 0.f, 0.f, 0.f); float s = 0.f;
            if (m < NP) { v = x4[m * 32 + cch * 8 + q]; s = g_rs[r * NP + m]; }
            uint32_t* p = &xs[row * XS_STR + q * 4];
            p[0] = f2tf32(v.x * s); p[1] = f2tf32(v.y * s);
            p[2] = f2tf32(v.z * s); p[3] = f2tf32(v.w * s);
        }
#pragma unroll
        for (int i = t; i < 32 * 64; i += 256)
            Ws[(i >> 6) * WS_STR + (i & 63)] = f2tf32(W[cch * 2048 + i]);
        __syncthreads();

#pragma unroll
        for (int ks = 0; ks < 4; ++ks) {
            const int kc = ks * 8;
            uint32_t a0 = xs[rowA + kc + t4];
            uint32_t a1 = xs[rowA + 8 * XS_STR + kc + t4];
            uint32_t a2 = xs[rowA + kc + t4 + 4];
            uint32_t a3 = xs[rowA + 8 * XS_STR + kc + t4 + 4];
            const int kb = (kc + t4) * WS_STR + g;
#pragma unroll
            for (int j = 0; j < 8; ++j) {
                uint32_t b0 = Ws[kb + j * 8];
                uint32_t b1 = Ws[kb + 4 * WS_STR + j * 8];
                mma_tf32(c[j][0], c[j][1], c[j][2], c[j][3], a0, a1, a2, a3, b0, b1);
            }
        }
        __syncthreads();
    }

    // epilogue: adjacent col pairs -> half2; row = 32 half2
    __half2* oh = (__half2*)g_hh;
    const int row0 = m0 + w * 16 + g;
#pragma unroll
    for (int j = 0; j < 8; ++j) {
        int h2i = j * 4 + t4;                 // (j*8 + t4*2)/2
        if (row0 < NP)
            oh[(r * NP + row0) * 32 + h2i] = __floats2half2_rn(c[j][0], c[j][1]);
        if (row0 + 8 < NP)
            oh[(r * NP + row0 + 8) * 32 + h2i] = __floats2half2_rn(c[j][2], c[j][3]);
    }
}

// ---------------- layer-1 gather: coalesced index loads + shfl broadcast ----------------
// Grid = NP*32 threads exactly (12500 blocks x 256): w < NP always, full-warp shfl safe.
__global__ void __launch_bounds__(256) gather1_kernel(const float* __restrict__ b0) {
    int w = (blockIdx.x * 256 + threadIdx.x) >> 5;   // dst node
    int lane = threadIdx.x & 31;
    float a0 = 0.f, a1 = 0.f;
#pragma unroll
    for (int r = 0; r < RREL; ++r) {
        int beg = g_rowptr[r * NP + w];
        int end = g_rowptr[r * NP + w + 1];
        float sc = g_rs[3 * NP + r * NP + w];
        const __half2* hb = (const __half2*)(g_hh + (size_t)r * NP * FH);
        float s0 = 0.f, s1 = 0.f;
        for (int base = beg; base < end; base += 32) {
            int n = end - base; if (n > 32) n = 32;
            int myi = (lane < n) ? g_csr[base + lane] : 0;   // ONE coalesced LDG / 32 edges
            int j = 0;
            for (; j + 4 <= n; j += 4) {
                int i0 = __shfl_sync(0xffffffffu, myi, j);
                int i1 = __shfl_sync(0xffffffffu, myi, j + 1);
                int i2 = __shfl_sync(0xffffffffu, myi, j + 2);
                int i3 = __shfl_sync(0xffffffffu, myi, j + 3);
                float2 v0 = __half22float2(hb[i0 * 32 + lane]);
                float2 v1 = __half22float2(hb[i1 * 32 + lane]);
                float2 v2 = __half22float2(hb[i2 * 32 + lane]);
                float2 v3 = __half22float2(hb[i3 * 32 + lane]);
                s0 += (v0.x + v1.x) + (v2.x + v3.x);
                s1 += (v0.y + v1.y) + (v2.y + v3.y);
            }
            for (; j < n; ++j) {
                int si = __shfl_sync(0xffffffffu, myi, j);
                float2 v = __half22float2(hb[si * 32 + lane]);
                s0 += v.x; s1 += v.y;
            }
        }
        a0 = fmaf(sc, s0, a0);
        a1 = fmaf(sc, s1, a1);
    }
    int f = 2 * lane;
    float o0 = fmaxf(a0 + b0[f]     + b0[FH + f]     + b0[2 * FH + f],     0.f);
    float o1 = fmaxf(a1 + b0[f + 1] + b0[FH + f + 1] + b0[2 * FH + f + 1], 0.f);
    *(float2*)&g_h1[w * FH + f] = make_float2(o0, o1);
}

// ---------------- layer-2 projection: tf32 MMA, fp16 output (R13 form) ----------------
// Tile 128(M) x 32(N), K=64. Ws cols: [0:16)=W_mu, [16:32)=W_ls.
#define X2_STR 68
#define W2_STR 40
__global__ void __launch_bounds__(256) proj2_kernel(const float* __restrict__ Wmu,
                                                    const float* __restrict__ Wls) {
    __shared__ uint32_t xs[128 * X2_STR];   // 34.8 KB
    __shared__ uint32_t Ws[64 * W2_STR];    // 10.2 KB
    const int r = blockIdx.y, t = threadIdx.x, m0 = blockIdx.x * 128;
    const int lane = t & 31, w = t >> 5;
    const int g = lane >> 2, t4 = lane & 3;

    for (int i = t; i < 64 * 16; i += 256) {
        int k = i >> 4, c = i & 15;
        Ws[k * W2_STR + c]      = f2tf32(Wmu[r * 1024 + i]);
        Ws[k * W2_STR + 16 + c] = f2tf32(Wls[r * 1024 + i]);
    }
    const float4* h4 = (const float4*)g_h1;
#pragma unroll
    for (int it = 0; it < 8; ++it) {
        int idx = t + it * 256;
        int row = idx >> 4, q = idx & 15;
        int m = m0 + row;
        float4 v = make_float4(0.f, 0.f, 0.f, 0.f); float s = 0.f;
        if (m < NP) { v = h4[m * 16 + q]; s = g_rs[r * NP + m]; }
        uint32_t* p = &xs[row * X2_STR + q * 4];
        p[0] = f2tf32(v.x * s); p[1] = f2tf32(v.y * s);
        p[2] = f2tf32(v.z * s); p[3] = f2tf32(v.w * s);
    }
    __syncthreads();

    float c[4][4];
#pragma unroll
    for (int j = 0; j < 4; ++j)
#pragma unroll
        for (int q = 0; q < 4; ++q) c[j][q] = 0.f;

    const int rowA = (w * 16 + g) * X2_STR;
#pragma unroll
    for (int ks = 0; ks < 8; ++ks) {
        const int kc = ks * 8;
        uint32_t a0 = xs[rowA + kc + t4];
        uint32_t a1 = xs[rowA + 8 * X2_STR + kc + t4];
        uint32_t a2 = xs[rowA + kc + t4 + 4];
        uint32_t a3 = xs[rowA + 8 * X2_STR + kc + t4 + 4];
        const int kb = (kc + t4) * W2_STR + g;
#pragma unroll
        for (int j = 0; j < 4; ++j) {
            uint32_t b0 = Ws[kb + j * 8];
            uint32_t b1 = Ws[kb + 4 * W2_STR + j * 8];
            mma_tf32(c[j][0], c[j][1], c[j][2], c[j][3], a0, a1, a2, a3, b0, b1);
        }
    }

    // epilogue: row = 16 half2
    __half2* oh = (__half2*)g_hh;
    const int row0 = m0 + w * 16 + g;
#pragma unroll
    for (int j = 0; j < 4; ++j) {
        int h2i = j * 4 + t4;
        if (row0 < NP)
            oh[(r * NP + row0) * 16 + h2i] = __floats2half2_rn(c[j][0], c[j][1]);
        if (row0 + 8 < NP)
            oh[(r * NP + row0 + 8) * 16 + h2i] = __floats2half2_rn(c[j][2], c[j][3]);
    }
}

// ---------------- layer-2 gather: coalesced index + shfl; fused reparameterization ----------------
__global__ void __launch_bounds__(256) gather2_kernel(const float* __restrict__ bmu,
                                                      const float* __restrict__ bls,
                                                      float* __restrict__ out) {
    int w = (blockIdx.x * 256 + threadIdx.x) >> 5;   // dst node
    int lane = threadIdx.x & 31;
    float acc = 0.f;
#pragma unroll
    for (int r = 0; r < RREL; ++r) {
        int beg = g_rowptr[r * NP + w];
        int end = g_rowptr[r * NP + w + 1];
        float sc = g_rs[3 * NP + r * NP + w];
        const __half* hb = g_hh + (size_t)r * NP * 32;
        float s0 = 0.f;
        for (int base = beg; base < end; base += 32) {
            int n = end - base; if (n > 32) n = 32;
            int myi = (lane < n) ? g_csr[base + lane] : 0;
            int j = 0;
            for (; j + 4 <= n; j += 4) {
                int i0 = __shfl_sync(0xffffffffu, myi, j);
                int i1 = __shfl_sync(0xffffffffu, myi, j + 1);
                int i2 = __shfl_sync(0xffffffffu, myi, j + 2);
                int i3 = __shfl_sync(0xffffffffu, myi, j + 3);
                float v0 = __half2float(hb[i0 * 32 + lane]);
                float v1 = __half2float(hb[i1 * 32 + lane]);
                float v2 = __half2float(hb[i2 * 32 + lane]);
                float v3 = __half2float(hb[i3 * 32 + lane]);
                s0 += (v0 + v1) + (v2 + v3);
            }
            for (; j < n; ++j) {
                int si = __shfl_sync(0xffffffffu, myi, j);
                s0 += __half2float(hb[si * 32 + lane]);
            }
        }
        acc = fmaf(sc, s0, acc);
    }
    // lanes 0..15: mean dims; lanes 16..31: log_std dims
    float bias = (lane < 16)
        ? (bmu[lane] + bmu[16 + lane] + bmu[32 + lane])
        : (bls[lane - 16] + bls[lane] + bls[lane + 16]);
    float val = acc + bias;
    float ls  = __shfl_sync(0xffffffffu, val, (lane + 16) & 31);
    uint32_t o0, o1;
    threefry_0_42(0u, (uint32_t)(w * 16 + lane), o0, o1);
    if (lane < 16)
        out[1000000 + w * 16 + lane] = val + jax_normal(o0 ^ o1) * expf(ls);
}

__global__ void score_kernel(const int* __restrict__ ps, const int* __restrict__ pd,
                             const int* __restrict__ ns, const int* __restrict__ nd,
                             float* __restrict__ out) {
    int i = blockIdx.x * 256 + threadIdx.x;
    if (i >= 2 * EPC) return;
    int s, d;
    if (i < EPC) { s = ps[i]; d = pd[i]; }
    else         { s = ns[i - EPC]; d = nd[i - EPC]; }
    const float4* h4 = (const float4*)(out + 1000000);
    float acc = 0.f;
#pragma unroll
    for (int q = 0; q < 4; ++q) {
        float4 a = h4[s * 4 + q], b = h4[d * 4 + q];
        acc += a.x * b.x + a.y * b.y + a.z * b.z + a.w * b.w;
    }
    out[i] = acc;
}

// ---------------- launch ----------------
extern "C" void kernel_launch(void* const* d_in, const int* in_sizes, int n_in,
                              void* d_out, int out_size) {
    const float* x   = (const float*)d_in[0];
    const float* W0  = (const float*)d_in[1];
    const float* b0  = (const float*)d_in[2];
    const float* Wmu = (const float*)d_in[3];
    const float* bmu = (const float*)d_in[4];
    const float* Wls = (const float*)d_in[5];
    const float* bls = (const float*)d_in[6];
    const int*   es  = (const int*)d_in[7];
    const int*   ed  = (const int*)d_in[8];
    const int*   ps  = (const int*)d_in[9];
    const int*   pd  = (const int*)d_in[10];
    const int*   ns  = (const int*)d_in[11];
    const int*   nd  = (const int*)d_in[12];
    float* out = (float*)d_out;

    const int GBLK = (NP * 32) / 256;             // 12500, exact

    zero_kernel         <<<(6 * NP + 255) / 256, 256>>>();
    deg_kernel          <<<(RREL * NE + 255) / 256, 256>>>(es, ed);
    scan_blocksum_kernel<<<SCAN_NB, SCAN_BLK>>>();
    scan_spine_kernel   <<<1, 1024>>>();
    scan_apply_kernel   <<<SCAN_NB, SCAN_BLK>>>();
    fill_csr_kernel     <<<(RREL * NE + 255) / 256, 256>>>(es, ed);
    proj1_kernel        <<<dim3(MBLK, RREL), 256>>>(x, W0);
    gather1_kernel      <<<GBLK, 256>>>(b0);
    proj2_kernel        <<<dim3(MBLK, RREL), 256>>>(Wmu, Wls);
    gather2_kernel      <<<GBLK, 256>>>(bmu, bls, out);
    score_kernel        <<<(2 * EPC + 255) / 256, 256>>>(ps, pd, ns, nd, out);
}

// round 16
// speedup vs baseline: 1.0865x; 1.0701x over previous
#include <cuda_runtime.h>
#include <cuda_fp16.h>
#include <cstdint>

#define NP   100000
#define RREL 3
#define NE   1600000
#define EPC  500000
#define FIN  128
#define FH   64
#define NDST (RREL * NP)          // 300000 scanned rows
#define SCAN_BLK 512
#define SCAN_NB  ((NDST + SCAN_BLK - 1) / SCAN_BLK)   // 586
#define MBLK 782                  // ceil(NP/128)

// ---------------- device scratch (static, allocation-free) ----------------
__device__ int    g_cnt[6 * NP];          // [0:3N) src counts, [3N:6N) dst counts
__device__ float  g_rs [6 * NP];          // rsqrt(max(count,1)) same layout
__device__ __half g_hh[RREL * NP * FH];   // per-relation projected features, fp16 (reused layer 2)
__device__ float  g_h1 [NP * FH];         // relu(hetero_conv1), fp32
__device__ int    g_rowptr[NDST + 1];     // CSR row pointers (relations concatenated)
__device__ int    g_cursor[NDST];         // fill cursors
__device__ int    g_csr[RREL * NE];       // src node per in-edge, grouped by (rel,dst)
__device__ int    g_bsum[SCAN_NB];        // scan spine

// Threefry-2x32, 20 rounds, key = (0, 42)  (jax.random.key(42))
__device__ __forceinline__ void threefry_0_42(uint32_t x0, uint32_t x1,
                                              uint32_t& o0, uint32_t& o1) {
    const uint32_t k0 = 0u, k1 = 42u, k2 = 0x1BD11BDAu ^ 0u ^ 42u;
    x0 += k0; x1 += k1;
#define TF_RND(Rv) { x0 += x1; x1 = __funnelshift_l(x1, x1, (Rv)); x1 ^= x0; }
    TF_RND(13) TF_RND(15) TF_RND(26) TF_RND(6)   x0 += k1; x1 += k2 + 1u;
    TF_RND(17) TF_RND(29) TF_RND(16) TF_RND(24)  x0 += k2; x1 += k0 + 2u;
    TF_RND(13) TF_RND(15) TF_RND(26) TF_RND(6)   x0 += k0; x1 += k1 + 3u;
    TF_RND(17) TF_RND(29) TF_RND(16) TF_RND(24)  x0 += k1; x1 += k2 + 4u;
    TF_RND(13) TF_RND(15) TF_RND(26) TF_RND(6)   x0 += k2; x1 += k0 + 5u;
#undef TF_RND
    o0 = x0; o1 = x1;
}

// bits -> jax-style standard normal (uniform in [lo,1) then sqrt(2)*erfinv)
__device__ __forceinline__ float jax_normal(uint32_t bits) {
    const float LO = -0.99999994f;
    float f = __uint_as_float((bits >> 9) | 0x3f800000u) - 1.0f;
    float u = fmaxf(f * 2.0f + LO, LO);
    return 1.41421356237309515f * erfinvf(u);
}

__device__ __forceinline__ uint32_t packh2(float a, float b) {
    __half2 h = __floats2half2_rn(a, b);
    return *(uint32_t*)&h;
}

// m16n8k16 fp16 MMA, fp32 accumulate. Fragment layouts match m16n8k8 C layout.
__device__ __forceinline__ void mma_f16(float& c0, float& c1, float& c2, float& c3,
                                        uint32_t a0, uint32_t a1, uint32_t a2, uint32_t a3,
                                        uint32_t b0, uint32_t b1) {
    asm volatile("mma.sync.aligned.m16n8k16.row.col.f32.f16.f16.f32 "
                 "{%0,%1,%2,%3},{%4,%5,%6,%7},{%8,%9},{%0,%1,%2,%3};"
                 : "+f"(c0), "+f"(c1), "+f"(c2), "+f"(c3)
                 : "r"(a0), "r"(a1), "r"(a2), "r"(a3), "r"(b0), "r"(b1));
}

// ---------------- setup kernels ----------------
__global__ void zero_kernel() {
    int i = blockIdx.x * 256 + threadIdx.x;
    if (i < 6 * NP) g_cnt[i] = 0;
}

__global__ void deg_kernel(const int* __restrict__ es, const int* __restrict__ ed) {
    int i = blockIdx.x * 256 + threadIdx.x;
    if (i >= RREL * NE) return;
    int r = i / NE;
    atomicAdd(&g_cnt[r * NP + es[i]], 1);
    atomicAdd(&g_cnt[3 * NP + r * NP + ed[i]], 1);
}

// ---- 3-kernel exclusive scan over dst counts ----
__global__ void scan_blocksum_kernel() {
    __shared__ int sm[SCAN_BLK];
    int i = blockIdx.x * SCAN_BLK + threadIdx.x;
    int v = (i < NDST) ? g_cnt[3 * NP + i] : 0;
    sm[threadIdx.x] = v;
    __syncthreads();
    for (int off = SCAN_BLK / 2; off > 0; off >>= 1) {
        if (threadIdx.x < off) sm[threadIdx.x] += sm[threadIdx.x + off];
        __syncthreads();
    }
    if (threadIdx.x == 0) g_bsum[blockIdx.x] = sm[0];
}

__global__ void scan_spine_kernel() {
    __shared__ int sm[1024];
    int t = threadIdx.x;
    int v = (t < SCAN_NB) ? g_bsum[t] : 0;
    sm[t] = v;
    __syncthreads();
    for (int off = 1; off < 1024; off <<= 1) {
        int add = (t >= off) ? sm[t - off] : 0;
        __syncthreads();
        sm[t] += add;
        __syncthreads();
    }
    if (t < SCAN_NB) g_bsum[t] = sm[t] - v;   // exclusive
}

__global__ void scan_apply_kernel() {
    __shared__ int sm[SCAN_BLK];
    int i = blockIdx.x * SCAN_BLK + threadIdx.x;
    int t = threadIdx.x;
    int v = (i < NDST) ? g_cnt[3 * NP + i] : 0;
    sm[t] = v;
    __syncthreads();
    for (int off = 1; off < SCAN_BLK; off <<= 1) {
        int add = (t >= off) ? sm[t - off] : 0;
        __syncthreads();
        sm[t] += add;
        __syncthreads();
    }
    if (i < NDST) {
        int excl = g_bsum[blockIdx.x] + sm[t] - v;
        g_rowptr[i] = excl;
        g_cursor[i] = excl;
        g_rs[i]          = rsqrtf(fmaxf((float)g_cnt[i], 1.0f));
        g_rs[3 * NP + i] = rsqrtf(fmaxf((float)v, 1.0f));
    }
    if (i == 0) g_rowptr[NDST] = RREL * NE;
}

__global__ void fill_csr_kernel(const int* __restrict__ es, const int* __restrict__ ed) {
    int i = blockIdx.x * 256 + threadIdx.x;
    if (i >= RREL * NE) return;
    int r = i / NE;
    int pos = atomicAdd(&g_cursor[r * NP + ed[i]], 1);
    g_csr[pos] = es[i];
}

// ---------------- layer-1 projection: fp16 m16n8k16 MMA, fp16 output ----------------
// Tile 128(M) x 64(N), K chunked x64 (2 chunks). 8 warps, warp w owns rows [16w,16w+16).
// xs: half2-packed k-pairs, stride 36 (banks 4g+t4 distinct).
// Ws: half2-packed k-pairs per col, stride 72 (banks 8t4+g distinct).
#define XS_STR 36
#define WS_STR 72
__global__ void __launch_bounds__(256) proj1_kernel(const float* __restrict__ x,
                                                    const float* __restrict__ W0) {
    __shared__ uint32_t xs[128 * XS_STR];   // 18.4 KB (32 half2 per row used)
    __shared__ uint32_t Ws[32 * WS_STR];    // 9.2 KB (32 k-pairs x 64 cols)
    const int r = blockIdx.y, t = threadIdx.x, m0 = blockIdx.x * 128;
    const int lane = t & 31, w = t >> 5;
    const int g = lane >> 2, t4 = lane & 3;

    float c[8][4];
#pragma unroll
    for (int j = 0; j < 8; ++j)
#pragma unroll
        for (int q = 0; q < 4; ++q) c[j][q] = 0.f;

    const float4* x4 = (const float4*)x;
    const float* W = W0 + r * FIN * FH;
    const int rowA = (w * 16 + g) * XS_STR;

    for (int cc = 0; cc < 2; ++cc) {
        // stage x[:, cc*64 : +64] scaled, packed as half2 k-pairs: 128 rows x 16 float4
#pragma unroll
        for (int it = 0; it < 8; ++it) {
            int idx = t + it * 256;
            int row = idx >> 4, q = idx & 15;
            int m = m0 + row;
            float4 v = make_float4(0.f, 0.f, 0.f, 0.f); float s = 0.f;
            if (m < NP) { v = x4[m * 32 + cc * 16 + q]; s = g_rs[r * NP + m]; }
            uint32_t* p = &xs[row * XS_STR + q * 2];
            p[0] = packh2(v.x * s, v.y * s);
            p[1] = packh2(v.z * s, v.w * s);
        }
        // stage W[cc*64 : +64, :] as half2 k-pairs: 32 pairs x 64 cols
#pragma unroll
        for (int i = t; i < 32 * 64; i += 256) {
            int k2 = i >> 6, n = i & 63;
            float w0 = W[(cc * 64 + 2 * k2) * FH + n];
            float w1 = W[(cc * 64 + 2 * k2 + 1) * FH + n];
            Ws[k2 * WS_STR + n] = packh2(w0, w1);
        }
        __syncthreads();

#pragma unroll
        for (int ks = 0; ks < 4; ++ks) {          // k16 steps
            const int base = ks * 8;               // half2 offset
            uint32_t a0 = xs[rowA + base + t4];
            uint32_t a1 = xs[rowA + 8 * XS_STR + base + t4];
            uint32_t a2 = xs[rowA + base + t4 + 4];
            uint32_t a3 = xs[rowA + 8 * XS_STR + base + t4 + 4];
            const int kb = (base + t4) * WS_STR + g;
#pragma unroll
            for (int j = 0; j < 8; ++j) {
                uint32_t b0 = Ws[kb + j * 8];
                uint32_t b1 = Ws[kb + 4 * WS_STR + j * 8];
                mma_f16(c[j][0], c[j][1], c[j][2], c[j][3], a0, a1, a2, a3, b0, b1);
            }
        }
        __syncthreads();
    }

    // epilogue: adjacent col pairs -> half2; row = 32 half2
    __half2* oh = (__half2*)g_hh;
    const int row0 = m0 + w * 16 + g;
#pragma unroll
    for (int j = 0; j < 8; ++j) {
        int h2i = j * 4 + t4;                 // (j*8 + t4*2)/2
        if (row0 < NP)
            oh[(r * NP + row0) * 32 + h2i] = __floats2half2_rn(c[j][0], c[j][1]);
        if (row0 + 8 < NP)
            oh[(r * NP + row0 + 8) * 32 + h2i] = __floats2half2_rn(c[j][2], c[j][3]);
    }
}

// ---------------- layer-1 gather: lane = half2 (dims 2l, 2l+1); 128B/warp/edge (R13) ----------------
__global__ void __launch_bounds__(256) gather1_kernel(const float* __restrict__ b0) {
    int w = (blockIdx.x * 256 + threadIdx.x) >> 5;   // dst node
    int lane = threadIdx.x & 31;
    if (w >= NP) return;
    float a0 = 0.f, a1 = 0.f;
#pragma unroll
    for (int r = 0; r < RREL; ++r) {
        int beg = g_rowptr[r * NP + w];
        int end = g_rowptr[r * NP + w + 1];
        float sc = g_rs[3 * NP + r * NP + w];
        const __half2* hb = (const __half2*)(g_hh + (size_t)r * NP * FH);
        float s0 = 0.f, s1 = 0.f;
        int e = beg;
        for (; e + 4 <= end; e += 4) {
            int i0 = g_csr[e], i1 = g_csr[e + 1], i2 = g_csr[e + 2], i3 = g_csr[e + 3];
            float2 v0 = __half22float2(hb[i0 * 32 + lane]);
            float2 v1 = __half22float2(hb[i1 * 32 + lane]);
            float2 v2 = __half22float2(hb[i2 * 32 + lane]);
            float2 v3 = __half22float2(hb[i3 * 32 + lane]);
            s0 += (v0.x + v1.x) + (v2.x + v3.x);
            s1 += (v0.y + v1.y) + (v2.y + v3.y);
        }
        for (; e < end; ++e) {
            float2 v = __half22float2(hb[g_csr[e] * 32 + lane]);
            s0 += v.x; s1 += v.y;
        }
        a0 = fmaf(sc, s0, a0);
        a1 = fmaf(sc, s1, a1);
    }
    int f = 2 * lane;
    float o0 = fmaxf(a0 + b0[f]     + b0[FH + f]     + b0[2 * FH + f],     0.f);
    float o1 = fmaxf(a1 + b0[f + 1] + b0[FH + f + 1] + b0[2 * FH + f + 1], 0.f);
    *(float2*)&g_h1[w * FH + f] = make_float2(o0, o1);
}

// ---------------- layer-2 projection: fp16 m16n8k16 MMA, fp16 output ----------------
// Tile 128(M) x 32(N), K=64 single chunk. Ws cols: [0:16)=W_mu, [16:32)=W_ls.
#define X2_STR 36
#define W2_STR 40
__global__ void __launch_bounds__(256) proj2_kernel(const float* __restrict__ Wmu,
                                                    const float* __restrict__ Wls) {
    __shared__ uint32_t xs[128 * X2_STR];   // 18.4 KB (32 half2 per row)
    __shared__ uint32_t Ws[32 * W2_STR];    // 5.1 KB (32 k-pairs x 32 cols)
    const int r = blockIdx.y, t = threadIdx.x, m0 = blockIdx.x * 128;
    const int lane = t & 31, w = t >> 5;
    const int g = lane >> 2, t4 = lane & 3;

    // stage W: k-pairs x 32 cols (mu | ls)
    for (int i = t; i < 32 * 32; i += 256) {
        int k2 = i >> 5, cidx = i & 31;
        float w0, w1;
        if (cidx < 16) {
            w0 = Wmu[r * 1024 + (2 * k2) * 16 + cidx];
            w1 = Wmu[r * 1024 + (2 * k2 + 1) * 16 + cidx];
        } else {
            w0 = Wls[r * 1024 + (2 * k2) * 16 + (cidx - 16)];
            w1 = Wls[r * 1024 + (2 * k2 + 1) * 16 + (cidx - 16)];
        }
        Ws[k2 * W2_STR + cidx] = packh2(w0, w1);
    }
    // stage h1 scaled: 128 rows x 16 float4 -> 32 half2
    const float4* h4 = (const float4*)g_h1;
#pragma unroll
    for (int it = 0; it < 8; ++it) {
        int idx = t + it * 256;
        int row = idx >> 4, q = idx & 15;
        int m = m0 + row;
        float4 v = make_float4(0.f, 0.f, 0.f, 0.f); float s = 0.f;
        if (m < NP) { v = h4[m * 16 + q]; s = g_rs[r * NP + m]; }
        uint32_t* p = &xs[row * X2_STR + q * 2];
        p[0] = packh2(v.x * s, v.y * s);
        p[1] = packh2(v.z * s, v.w * s);
    }
    __syncthreads();

    float c[4][4];
#pragma unroll
    for (int j = 0; j < 4; ++j)
#pragma unroll
        for (int q = 0; q < 4; ++q) c[j][q] = 0.f;

    const int rowA = (w * 16 + g) * X2_STR;
#pragma unroll
    for (int ks = 0; ks < 4; ++ks) {
        const int base = ks * 8;
        uint32_t a0 = xs[rowA + base + t4];
        uint32_t a1 = xs[rowA + 8 * X2_STR + base + t4];
        uint32_t a2 = xs[rowA + base + t4 + 4];
        uint32_t a3 = xs[rowA + 8 * X2_STR + base + t4 + 4];
        const int kb = (base + t4) * W2_STR + g;
#pragma unroll
        for (int j = 0; j < 4; ++j) {
            uint32_t b0 = Ws[kb + j * 8];
            uint32_t b1 = Ws[kb + 4 * W2_STR + j * 8];
            mma_f16(c[j][0], c[j][1], c[j][2], c[j][3], a0, a1, a2, a3, b0, b1);
        }
    }

    // epilogue: row = 16 half2
    __half2* oh = (__half2*)g_hh;
    const int row0 = m0 + w * 16 + g;
#pragma unroll
    for (int j = 0; j < 4; ++j) {
        int h2i = j * 4 + t4;
        if (row0 < NP)
            oh[(r * NP + row0) * 16 + h2i] = __floats2half2_rn(c[j][0], c[j][1]);
        if (row0 + 8 < NP)
            oh[(r * NP + row0 + 8) * 16 + h2i] = __floats2half2_rn(c[j][2], c[j][3]);
    }
}

// ---------------- layer-2 gather — fp16 rows (64B/edge), fused reparameterization (R13) ----------------
__global__ void __launch_bounds__(256) gather2_kernel(const float* __restrict__ bmu,
                                                      const float* __restrict__ bls,
                                                      float* __restrict__ out) {
    int w = (blockIdx.x * 256 + threadIdx.x) >> 5;   // dst node
    int lane = threadIdx.x & 31;
    if (w >= NP) return;
    float acc = 0.f;
#pragma unroll
    for (int r = 0; r < RREL; ++r) {
        int beg = g_rowptr[r * NP + w];
        int end = g_rowptr[r * NP + w + 1];
        float sc = g_rs[3 * NP + r * NP + w];
        const __half* hb = g_hh + (size_t)r * NP * 32;
        float s0 = 0.f;
        int e = beg;
        for (; e + 4 <= end; e += 4) {
            int i0 = g_csr[e], i1 = g_csr[e + 1], i2 = g_csr[e + 2], i3 = g_csr[e + 3];
            float v0 = __half2float(hb[i0 * 32 + lane]);
            float v1 = __half2float(hb[i1 * 32 + lane]);
            float v2 = __half2float(hb[i2 * 32 + lane]);
            float v3 = __half2float(hb[i3 * 32 + lane]);
            s0 += (v0 + v1) + (v2 + v3);
        }
        for (; e < end; ++e) s0 += __half2float(hb[g_csr[e] * 32 + lane]);
        acc = fmaf(sc, s0, acc);
    }
    // lanes 0..15: mean dims; lanes 16..31: log_std dims
    float bias = (lane < 16)
        ? (bmu[lane] + bmu[16 + lane] + bmu[32 + lane])
        : (bls[lane - 16] + bls[lane] + bls[lane + 16]);
    float val = acc + bias;
    float ls  = __shfl_sync(0xffffffffu, val, (lane + 16) & 31);
    uint32_t o0, o1;
    threefry_0_42(0u, (uint32_t)(w * 16 + lane), o0, o1);
    if (lane < 16)
        out[1000000 + w * 16 + lane] = val + jax_normal(o0 ^ o1) * expf(ls);
}

__global__ void score_kernel(const int* __restrict__ ps, const int* __restrict__ pd,
                             const int* __restrict__ ns, const int* __restrict__ nd,
                             float* __restrict__ out) {
    int i = blockIdx.x * 256 + threadIdx.x;
    if (i >= 2 * EPC) return;
    int s, d;
    if (i < EPC) { s = ps[i]; d = pd[i]; }
    else         { s = ns[i - EPC]; d = nd[i - EPC]; }
    const float4* h4 = (const float4*)(out + 1000000);
    float acc = 0.f;
#pragma unroll
    for (int q = 0; q < 4; ++q) {
        float4 a = h4[s * 4 + q], b = h4[d * 4 + q];
        acc += a.x * b.x + a.y * b.y + a.z * b.z + a.w * b.w;
    }
    out[i] = acc;
}

// ---------------- launch ----------------
extern "C" void kernel_launch(void* const* d_in, const int* in_sizes, int n_in,
                              void* d_out, int out_size) {
    const float* x   = (const float*)d_in[0];
    const float* W0  = (const float*)d_in[1];
    const float* b0  = (const float*)d_in[2];
    const float* Wmu = (const float*)d_in[3];
    const float* bmu = (const float*)d_in[4];
    const float* Wls = (const float*)d_in[5];
    const float* bls = (const float*)d_in[6];
    const int*   es  = (const int*)d_in[7];
    const int*   ed  = (const int*)d_in[8];
    const int*   ps  = (const int*)d_in[9];
    const int*   pd  = (const int*)d_in[10];
    const int*   ns  = (const int*)d_in[11];
    const int*   nd  = (const int*)d_in[12];
    float* out = (float*)d_out;

    const int GBLK = (NP * 32 + 255) / 256;       // warp-per-node grids

    zero_kernel         <<<(6 * NP + 255) / 256, 256>>>();
    deg_kernel          <<<(RREL * NE + 255) / 256, 256>>>(es, ed);
    scan_blocksum_kernel<<<SCAN_NB, SCAN_BLK>>>();
    scan_spine_kernel   <<<1, 1024>>>();
    scan_apply_kernel   <<<SCAN_NB, SCAN_BLK>>>();
    fill_csr_kernel     <<<(RREL * NE + 255) / 256, 256>>>(es, ed);
    proj1_kernel        <<<dim3(MBLK, RREL), 256>>>(x, W0);
    gather1_kernel      <<<GBLK, 256>>>(b0);
    proj2_kernel        <<<dim3(MBLK, RREL), 256>>>(Wmu, Wls);
    gather2_kernel      <<<GBLK, 256>>>(bmu, bls, out);
    score_kernel        <<<(2 * EPC + 255) / 256, 256>>>(ps, pd, ns, nd, out);
}